// round 14
// baseline (speedup 1.0000x reference)
#include <cuda_runtime.h>
#include <cuda_fp16.h>
#include <stdint.h>
#include <math.h>

#define D     1024
#define NH    16
#define HD    64
#define FF    4096
#define SEQ   2048
#define BATCH 2
#define MTOK  (BATCH*SEQ)   // 4096 rows
#define D3    (3*D)

// ---------------- scratch (static device globals; no allocs) ----------------
__device__ float g_attnres[MTOK*(size_t)D];
__device__ float g_h[MTOK*(size_t)D];
__device__ float g_ff2[MTOK*(size_t)D];
__device__ float g_bqkv[D3];

__device__ __half g_x16[MTOK*(size_t)D];
__device__ __half g_qkv16[MTOK*(size_t)D3];
__device__ __half g_ctx16[MTOK*(size_t)D];
__device__ __half g_h16[MTOK*(size_t)D];
__device__ __half g_f116[MTOK*(size_t)FF];
__device__ __half g_wqkv16[D*(size_t)D3];
__device__ __half g_wo16[D*(size_t)D];
__device__ __half g_w116[D*(size_t)FF];
__device__ __half g_w216[FF*(size_t)D];

// ---------------- helpers --------------------------------------------------
__device__ __forceinline__ unsigned smem_u32(const void* p) {
    return (unsigned)__cvta_generic_to_shared(p);
}
__device__ __forceinline__ void ldsm_x4(unsigned r[4], unsigned addr) {
    asm volatile("ldmatrix.sync.aligned.m8n8.x4.shared.b16 {%0,%1,%2,%3}, [%4];"
                 : "=r"(r[0]), "=r"(r[1]), "=r"(r[2]), "=r"(r[3]) : "r"(addr));
}
__device__ __forceinline__ void ldsm_x4t(unsigned r[4], unsigned addr) {
    asm volatile("ldmatrix.sync.aligned.m8n8.x4.trans.shared.b16 {%0,%1,%2,%3}, [%4];"
                 : "=r"(r[0]), "=r"(r[1]), "=r"(r[2]), "=r"(r[3]) : "r"(addr));
}
__device__ __forceinline__ void mma_f16(float c[4], const unsigned a[4], const unsigned b[2]) {
    asm volatile("mma.sync.aligned.m16n8k16.row.col.f32.f16.f16.f32 "
                 "{%0,%1,%2,%3}, {%4,%5,%6,%7}, {%8,%9}, {%0,%1,%2,%3};"
                 : "+f"(c[0]), "+f"(c[1]), "+f"(c[2]), "+f"(c[3])
                 : "r"(a[0]), "r"(a[1]), "r"(a[2]), "r"(a[3]), "r"(b[0]), "r"(b[1]));
}
__device__ __forceinline__ void cp16(unsigned dst, const void* src) {
    asm volatile("cp.async.cg.shared.global [%0], [%1], 16;" :: "r"(dst), "l"(src) : "memory");
}
__device__ __forceinline__ void cp_commit() { asm volatile("cp.async.commit_group;" ::: "memory"); }
template <int N>
__device__ __forceinline__ void cp_wait() { asm volatile("cp.async.wait_group %0;" :: "n"(N) : "memory"); }

// ==================== persistent fp16 GEMM ==================================
// 128x128 block tile, 64x32 warp tile, BK=64, 3-stage ring that never drains
// across tiles; grid = 296 CTAs (148 SMs x occ 2).
#define ASTR 72
#define BSTR 136
#define GEMM_GRID 296
struct GSmem {
    __half Ah[3][128][ASTR];
    __half Bh[3][64][BSTR];
};

// EPI: 0 = fp32 C; 1 = GELU then fp16; 2 = fp16
template <int EPI>
__global__ __launch_bounds__(256, 2) void gemm_f16(
    const __half* __restrict__ Ag, const __half* __restrict__ Bg,
    const float* __restrict__ bias,
    float* __restrict__ C, __half* __restrict__ Ch,
    int M, int N, int K)
{
    extern __shared__ char smem_raw[];
    GSmem& sm = *reinterpret_cast<GSmem*>(smem_raw);

    const int tid  = threadIdx.x;
    const int lane = tid & 31;
    const int wid  = tid >> 5;
    const int warpM = wid & 1;
    const int warpN = wid >> 1;
    const int bid  = blockIdx.x;
    const int nbx  = N >> 7;
    const int tiles = (M >> 7) * nbx;
    const int KT = K / 64;

    if (bid >= tiles) return;
    const int myTiles = (tiles - bid - 1) / GEMM_GRID + 1;
    const int L = myTiles * KT;

    auto load_stage = [&](int l) {
        const int st = l % 3;
        const int j  = l / KT;
        const int kt = l - j * KT;
        const int tile = bid + j * GEMM_GRID;
        const int bx = tile % nbx;
        const int by = tile / nbx;
        #pragma unroll
        for (int q = 0; q < 4; q++) {
            int f = tid + q * 256;
            int r = f >> 3, c = (f & 7) * 8;
            cp16(smem_u32(&sm.Ah[st][r][c]), Ag + (size_t)(by * 128 + r) * K + kt * 64 + c);
        }
        #pragma unroll
        for (int q = 0; q < 4; q++) {
            int f = tid + q * 256;
            int r = f >> 4, c = (f & 15) * 8;
            cp16(smem_u32(&sm.Bh[st][r][c]), Bg + (size_t)(kt * 64 + r) * N + bx * 128 + c);
        }
    };

    load_stage(0); cp_commit();
    if (L > 1) { load_stage(1); cp_commit(); }

    const int arow = warpM * 64 + (lane & 15);
    const int acol8 = (lane >> 4) * 8;
    const int brow = ((lane >> 3) & 1) * 8 + (lane & 7);
    const int bcol = warpN * 32 + ((lane >> 4) & 1) * 8;
    const int g  = lane >> 2;
    const int t2 = (lane & 3) * 2;

    float acc[4][4][4];
    #pragma unroll
    for (int i = 0; i < 4; i++)
        #pragma unroll
        for (int j = 0; j < 4; j++)
            #pragma unroll
            for (int r = 0; r < 4; r++) acc[i][j][r] = 0.f;

    for (int l = 0; l < L; l++) {
        if (l + 1 < L) cp_wait<1>(); else cp_wait<0>();
        __syncthreads();
        if (l + 2 < L) { load_stage(l + 2); cp_commit(); }

        const int st = l % 3;
        #pragma unroll
        for (int ks = 0; ks < 4; ks++) {
            const int k0 = ks * 16;
            unsigned ah[4][4];
            #pragma unroll
            for (int mi = 0; mi < 4; mi++)
                ldsm_x4(ah[mi], smem_u32(&sm.Ah[st][arow + mi * 16][k0 + acol8]));
            #pragma unroll
            for (int nn = 0; nn < 2; nn++) {
                unsigned bh[4];
                ldsm_x4t(bh, smem_u32(&sm.Bh[st][k0 + brow][bcol + nn * 16]));
                #pragma unroll
                for (int mi = 0; mi < 4; mi++) {
                    mma_f16(acc[mi][2*nn],   ah[mi], bh);
                    mma_f16(acc[mi][2*nn+1], ah[mi], bh + 2);
                }
            }
        }

        // tile finished? -> epilogue + reset acc
        if (l % KT == KT - 1) {
            const int j = l / KT;
            const int tile = bid + j * GEMM_GRID;
            const int bx = tile % nbx;
            const int by = tile / nbx;
            #pragma unroll
            for (int mi = 0; mi < 4; mi++) {
                #pragma unroll
                for (int ni = 0; ni < 4; ni++) {
                    int row0 = by * 128 + warpM * 64 + mi * 16 + g;
                    int col  = bx * 128 + warpN * 32 + ni * 8 + t2;
                    float b0 = bias[col], b1 = bias[col + 1];
                    #pragma unroll
                    for (int half = 0; half < 2; half++) {
                        int row = row0 + half * 8;
                        float v0 = acc[mi][ni][half * 2 + 0] + b0;
                        float v1 = acc[mi][ni][half * 2 + 1] + b1;
                        if (EPI >= 1) {
                            if (EPI == 1) {
                                v0 = 0.5f * v0 * (1.f + erff(v0 * 0.70710678118654752f));
                                v1 = 0.5f * v1 * (1.f + erff(v1 * 0.70710678118654752f));
                            }
                            *(__half2*)(Ch + (size_t)row * N + col) = __floats2half2_rn(v0, v1);
                        } else {
                            float2 o; o.x = v0; o.y = v1;
                            *(float2*)(C + (size_t)row * N + col) = o;
                        }
                        acc[mi][ni][half * 2 + 0] = 0.f;
                        acc[mi][ni][half * 2 + 1] = 0.f;
                    }
                }
            }
        }
    }
}

// ---------------- merged fp32 -> fp16 conversion + bias concat --------------
__global__ __launch_bounds__(256) void convert_all(
    const float* __restrict__ x,  const float* __restrict__ Wq,
    const float* __restrict__ Wk, const float* __restrict__ Wv,
    const float* __restrict__ Wo, const float* __restrict__ W1,
    const float* __restrict__ W2,
    const float* __restrict__ bq, const float* __restrict__ bk,
    const float* __restrict__ bv,
    __half* __restrict__ x16, __half* __restrict__ wqkv,
    __half* __restrict__ wo,  __half* __restrict__ w1, __half* __restrict__ w2,
    float* __restrict__ bqkv)
{
    const int bid = blockIdx.x;
    const int tid = threadIdx.x;

    if (bid >= 32768) {
        int i = (bid - 32768) * 512 + tid * 2;
        if (i < D3) {
            int seg = i >> 10, off = i & (D - 1);
            const float* s = (seg == 0) ? bq : (seg == 1) ? bk : bv;
            bqkv[i]     = s[off];
            bqkv[i + 1] = s[off + 1];
        }
        return;
    }

    const float* src;
    __half* dst;
    int base;
    int qkvOff = -1;
    if (bid < 8192)       { src = x;  dst = x16; base = bid; }
    else if (bid < 10240) { src = Wq; dst = wqkv; base = bid - 8192;  qkvOff = 0; }
    else if (bid < 12288) { src = Wk; dst = wqkv; base = bid - 10240; qkvOff = D; }
    else if (bid < 14336) { src = Wv; dst = wqkv; base = bid - 12288; qkvOff = 2 * D; }
    else if (bid < 16384) { src = Wo; dst = wo;  base = bid - 14336; }
    else if (bid < 24576) { src = W1; dst = w1;  base = bid - 16384; }
    else                  { src = W2; dst = w2;  base = bid - 24576; }

    int i = (base * 256 + tid) * 2;
    float2 v = *(const float2*)(src + i);
    __half2 hv = __floats2half2_rn(v.x, v.y);
    if (qkvOff >= 0) {
        int r = i >> 10;
        int c = i & (D - 1);
        *(__half2*)(dst + (size_t)r * D3 + qkvOff + c) = hv;
    } else {
        *(__half2*)(dst + i) = hv;
    }
}

// ==================== fp16 mma flash attention (R13) =========================
#define QPAD 72
struct AttnSmem {
    __half Qh[128][QPAD];
    __half Kh[3][64][QPAD];
    __half Vh[3][64][QPAD];
};

__global__ __launch_bounds__(256, 2) void attn_mma(
    const __half* __restrict__ qg, const __half* __restrict__ kg,
    const __half* __restrict__ vg, __half* __restrict__ ctx, int ld)
{
    extern __shared__ char smem_raw[];
    AttnSmem& sm = *reinterpret_cast<AttnSmem*>(smem_raw);

    const int tid  = threadIdx.x;
    const int lane = tid & 31;
    const int w    = tid >> 5;
    const int g    = lane >> 2;
    const int t    = lane & 3;

    const int qt = (int)gridDim.x - 1 - (int)blockIdx.x;
    const int h  = blockIdx.y;
    const int b  = blockIdx.z;
    const size_t q0 = (size_t)b * SEQ + qt * 128;
    const int hcol = h * HD;
    const float SC = 0.125f * 1.44269504088896340736f;

    #pragma unroll
    for (int l = 0; l < 4; l++) {
        int f = tid + l * 256;
        int r = f >> 3, c = (f & 7) * 8;
        cp16(smem_u32(&sm.Qh[r][c]), qg + (q0 + r) * ld + hcol + c);
    }

    auto load_kv = [&](int st, int kt) {
        const size_t kr0 = (size_t)b * SEQ + kt * 64;
        #pragma unroll
        for (int l = 0; l < 2; l++) {
            int f = tid + l * 256;
            int r = f >> 3, c = (f & 7) * 8;
            const size_t go = (kr0 + r) * ld + hcol + c;
            cp16(smem_u32(&sm.Kh[st][r][c]), kg + go);
            cp16(smem_u32(&sm.Vh[st][r][c]), vg + go);
        }
    };

    const int ktiles = qt * 2 + 2;
    load_kv(0, 0); cp_commit();
    load_kv(1, 1); cp_commit();

    const int qbase = qt * 128 + w * 16;
    const int qmax  = qbase + 15;

    const int krow_lo = (lane & 7) + ((lane >> 4) & 1) * 8;
    const int kcol8   = ((lane >> 3) & 1) * 8;
    const int vrow    = lane & 15;
    const int vcol8   = ((lane >> 4) & 1) * 8;

    unsigned qf[4][4];
    float m[2] = {-1e30f, -1e30f};
    float lsum[2] = {0.f, 0.f};
    float acc[8][4];
    #pragma unroll
    for (int nf = 0; nf < 8; nf++)
        #pragma unroll
        for (int i = 0; i < 4; i++) acc[nf][i] = 0.f;

    const __half2 sch = __floats2half2_rn(SC, SC);

    for (int kt = 0; kt < ktiles; kt++) {
        const int st = kt % 3;
        if (kt + 1 >= ktiles) cp_wait<0>(); else cp_wait<1>();
        __syncthreads();
        if (kt + 2 < ktiles) { load_kv((kt + 2) % 3, kt + 2); cp_commit(); }

        if (kt == 0) {
            #pragma unroll
            for (int kf = 0; kf < 4; kf++) {
                int r = w * 16 + (lane & 15);
                int c = kf * 16 + (lane >> 4) * 8;
                ldsm_x4(qf[kf], smem_u32(&sm.Qh[r][c]));
                #pragma unroll
                for (int i = 0; i < 4; i++) {
                    __half2 qh2 = __hmul2(*(__half2*)&qf[kf][i], sch);
                    qf[kf][i] = *(unsigned*)&qh2;
                }
            }
        }

        const int kbase = kt * 64;
        if (kbase > qmax) continue;

        float s[8][4];
        #pragma unroll
        for (int nf = 0; nf < 8; nf++)
            #pragma unroll
            for (int i = 0; i < 4; i++) s[nf][i] = 0.f;

        #pragma unroll
        for (int nf2 = 0; nf2 < 4; nf2++) {
            #pragma unroll
            for (int kf = 0; kf < 4; kf++) {
                unsigned kb[4];
                int kr = nf2 * 16 + krow_lo;
                int kc = kf * 16 + kcol8;
                ldsm_x4(kb, smem_u32(&sm.Kh[st][kr][kc]));
                mma_f16(s[2*nf2],     qf[kf], kb);
                mma_f16(s[2*nf2 + 1], qf[kf], kb + 2);
            }
        }

        if (kbase + 63 > qbase) {
            #pragma unroll
            for (int nf = 0; nf < 8; nf++) {
                #pragma unroll
                for (int i = 0; i < 4; i++) {
                    int key = kbase + nf * 8 + 2 * t + (i & 1);
                    int qry = qbase + g + (i >> 1) * 8;
                    s[nf][i] = (key > qry) ? -1e30f : s[nf][i];
                }
            }
        }

        float cfac[2];
        unsigned ph[4][4];
        #pragma unroll
        for (int r = 0; r < 2; r++) {
            float vmax = -1e30f;
            #pragma unroll
            for (int nf = 0; nf < 8; nf++) {
                vmax = fmaxf(vmax, s[nf][2 * r]);
                vmax = fmaxf(vmax, s[nf][2 * r + 1]);
            }
            vmax = fmaxf(vmax, __shfl_xor_sync(0xffffffffu, vmax, 1));
            vmax = fmaxf(vmax, __shfl_xor_sync(0xffffffffu, vmax, 2));
            float mn = fmaxf(m[r], vmax);
            cfac[r] = exp2f(m[r] - mn);
            m[r] = mn;
            float rowsum = 0.f;
            #pragma unroll
            for (int nf = 0; nf < 8; nf++) {
                __half2 hd = __floats2half2_rn(s[nf][2 * r] - mn, s[nf][2 * r + 1] - mn);
                unsigned e;
                asm("ex2.approx.f16x2 %0, %1;" : "=r"(e) : "r"(*(unsigned*)&hd));
                ph[nf >> 1][(nf & 1) * 2 + r] = e;
                float2 pf = __half22float2(*(__half2*)&e);
                rowsum += pf.x + pf.y;
            }
            rowsum += __shfl_xor_sync(0xffffffffu, rowsum, 1);
            rowsum += __shfl_xor_sync(0xffffffffu, rowsum, 2);
            lsum[r] = lsum[r] * cfac[r] + rowsum;
        }
        #pragma unroll
        for (int nf = 0; nf < 8; nf++) {
            acc[nf][0] *= cfac[0]; acc[nf][1] *= cfac[0];
            acc[nf][2] *= cfac[1]; acc[nf][3] *= cfac[1];
        }

        #pragma unroll
        for (int nf2 = 0; nf2 < 4; nf2++) {
            #pragma unroll
            for (int kf = 0; kf < 4; kf++) {
                unsigned vb[4];
                int vr = kf * 16 + vrow;
                int vc = nf2 * 16 + vcol8;
                ldsm_x4t(vb, smem_u32(&sm.Vh[st][vr][vc]));
                mma_f16(acc[2*nf2],     ph[kf], vb);
                mma_f16(acc[2*nf2 + 1], ph[kf], vb + 2);
            }
        }
    }

    const float inv0 = 1.f / lsum[0];
    const float inv1 = 1.f / lsum[1];
    #pragma unroll
    for (int nf = 0; nf < 8; nf++) {
        int col = hcol + nf * 8 + 2 * t;
        size_t row0 = q0 + w * 16 + g;
        *(__half2*)(ctx + row0 * D + col)       = __floats2half2_rn(acc[nf][0] * inv0, acc[nf][1] * inv0);
        *(__half2*)(ctx + (row0 + 8) * D + col) = __floats2half2_rn(acc[nf][2] * inv1, acc[nf][3] * inv1);
    }
}

// ---------------- fused residual add + LayerNorm (float4 I/O) ---------------
template <int WB>
__global__ __launch_bounds__(256) void add_ln(
    const float* __restrict__ Ain, const float* __restrict__ Bin,
    const float* __restrict__ g, const float* __restrict__ be,
    float* __restrict__ out, __half* __restrict__ oh)
{
    const int row = blockIdx.x;
    const int tid = threadIdx.x;
    const float* a = Ain + (size_t)row * D;
    const float* b = Bin + (size_t)row * D;

    float4 va = *(const float4*)(a + tid * 4);
    float4 vb = *(const float4*)(b + tid * 4);
    float v0 = va.x + vb.x, v1 = va.y + vb.y, v2 = va.z + vb.z, v3 = va.w + vb.w;

    float s  = v0 + v1 + v2 + v3;
    float s2 = v0*v0 + v1*v1 + v2*v2 + v3*v3;
    #pragma unroll
    for (int off = 16; off > 0; off >>= 1) {
        s  += __shfl_xor_sync(0xffffffffu, s,  off);
        s2 += __shfl_xor_sync(0xffffffffu, s2, off);
    }
    __shared__ float sh[2][8];
    if ((tid & 31) == 0) { sh[0][tid >> 5] = s; sh[1][tid >> 5] = s2; }
    __syncthreads();
    float ts = 0.f, t2 = 0.f;
    #pragma unroll
    for (int w = 0; w < 8; w++) { ts += sh[0][w]; t2 += sh[1][w]; }

    const float mu  = ts * (1.f / D);
    const float var = t2 * (1.f / D) - mu * mu;
    const float inv = rsqrtf(var + 1e-5f);

    float4 gg = *(const float4*)(g + tid * 4);
    float4 bb = *(const float4*)(be + tid * 4);
    float o0 = (v0 - mu) * inv * gg.x + bb.x;
    float o1 = (v1 - mu) * inv * gg.y + bb.y;
    float o2 = (v2 - mu) * inv * gg.z + bb.z;
    float o3 = (v3 - mu) * inv * gg.w + bb.w;

    float4 ov; ov.x = o0; ov.y = o1; ov.z = o2; ov.w = o3;
    *(float4*)(out + (size_t)row * D + tid * 4) = ov;
    if (WB) {
        *(__half2*)(oh + (size_t)row * D + tid * 4)     = __floats2half2_rn(o0, o1);
        *(__half2*)(oh + (size_t)row * D + tid * 4 + 2) = __floats2half2_rn(o2, o3);
    }
}

// ---------------- launch -----------------------------------------------------
extern "C" void kernel_launch(void* const* d_in, const int* in_sizes, int n_in,
                              void* d_out, int out_size)
{
    const float* x    = (const float*)d_in[0];
    const float* Wq   = (const float*)d_in[1];
    const float* bq   = (const float*)d_in[2];
    const float* Wk   = (const float*)d_in[3];
    const float* bk   = (const float*)d_in[4];
    const float* Wv   = (const float*)d_in[5];
    const float* bv   = (const float*)d_in[6];
    const float* Wo   = (const float*)d_in[7];
    const float* bo   = (const float*)d_in[8];
    const float* ln1g = (const float*)d_in[9];
    const float* ln1b = (const float*)d_in[10];
    const float* W1   = (const float*)d_in[11];
    const float* b1   = (const float*)d_in[12];
    const float* W2   = (const float*)d_in[13];
    const float* b2   = (const float*)d_in[14];
    const float* ln2g = (const float*)d_in[15];
    const float* ln2b = (const float*)d_in[16];
    float* out = (float*)d_out;

    float *attnres, *h, *ff2, *bqkv;
    cudaGetSymbolAddress((void**)&attnres, g_attnres);
    cudaGetSymbolAddress((void**)&h,    g_h);
    cudaGetSymbolAddress((void**)&ff2,  g_ff2);
    cudaGetSymbolAddress((void**)&bqkv, g_bqkv);

    __half *x16,*qkv16,*ctx16,*h16,*f116,*wqkv16,*wo16,*w116,*w216;
    cudaGetSymbolAddress((void**)&x16,   g_x16);
    cudaGetSymbolAddress((void**)&qkv16, g_qkv16);
    cudaGetSymbolAddress((void**)&ctx16, g_ctx16);
    cudaGetSymbolAddress((void**)&h16,   g_h16);
    cudaGetSymbolAddress((void**)&f116,  g_f116);
    cudaGetSymbolAddress((void**)&wqkv16,g_wqkv16);
    cudaGetSymbolAddress((void**)&wo16,  g_wo16);
    cudaGetSymbolAddress((void**)&w116,  g_w116);
    cudaGetSymbolAddress((void**)&w216,  g_w216);

    static int attr_set = 0;
    if (!attr_set) {
        cudaFuncSetAttribute(gemm_f16<0>, cudaFuncAttributeMaxDynamicSharedMemorySize, (int)sizeof(GSmem));
        cudaFuncSetAttribute(gemm_f16<1>, cudaFuncAttributeMaxDynamicSharedMemorySize, (int)sizeof(GSmem));
        cudaFuncSetAttribute(gemm_f16<2>, cudaFuncAttributeMaxDynamicSharedMemorySize, (int)sizeof(GSmem));
        cudaFuncSetAttribute(attn_mma, cudaFuncAttributeMaxDynamicSharedMemorySize, (int)sizeof(AttnSmem));
        attr_set = 1;
    }
    const int SG = (int)sizeof(GSmem);
    const int SA = (int)sizeof(AttnSmem);

    // ---- conversions + bias concat ----
    convert_all<<<32774, 256>>>(x, Wq, Wk, Wv, Wo, W1, W2, bq, bk, bv,
                                x16, wqkv16, wo16, w116, w216, bqkv);

    // ---- merged QKV projection (persistent grid) ----
    gemm_f16<2><<<GEMM_GRID, 256, SG>>>(x16, wqkv16, bqkv, nullptr, qkv16, MTOK, D3, D);

    // ---- flash attention ----
    dim3 gAttn(SEQ / 128, NH, BATCH);
    attn_mma<<<gAttn, 256, SA>>>(qkv16, qkv16 + D, qkv16 + 2*D, ctx16, D3);

    // ---- O projection ----
    gemm_f16<0><<<GEMM_GRID, 256, SG>>>(ctx16, wo16, bo, attnres, nullptr, MTOK, D, D);

    // ---- LN1 ----
    add_ln<1><<<MTOK, 256>>>(attnres, x, ln1g, ln1b, h, h16);

    // ---- FFN ----
    gemm_f16<1><<<GEMM_GRID, 256, SG>>>(h16, w116, b1, nullptr, f116, MTOK, FF, D);
    gemm_f16<0><<<GEMM_GRID, 256, SG>>>(f116, w216, b2, ff2, nullptr, MTOK, D, FF);

    // ---- LN2 ----
    add_ln<0><<<MTOK, 256>>>(ff2, h, ln2g, ln2b, out, nullptr);
}

// round 15
// speedup vs baseline: 1.0484x; 1.0484x over previous
#include <cuda_runtime.h>
#include <cuda_fp16.h>
#include <stdint.h>
#include <math.h>

#define D     1024
#define NH    16
#define HD    64
#define FF    4096
#define SEQ   2048
#define BATCH 2
#define MTOK  (BATCH*SEQ)   // 4096 rows
#define D3    (3*D)

// ---------------- scratch (static device globals; no allocs) ----------------
__device__ float g_attnres[MTOK*(size_t)D];
__device__ float g_h[MTOK*(size_t)D];
__device__ float g_ff2[MTOK*(size_t)D];
__device__ float g_bqkv[D3];

__device__ __half g_x16[MTOK*(size_t)D];
__device__ __half g_qkv16[MTOK*(size_t)D3];
__device__ __half g_ctx16[MTOK*(size_t)D];
__device__ __half g_h16[MTOK*(size_t)D];
__device__ __half g_f116[MTOK*(size_t)FF];
__device__ __half g_wqkv16[D*(size_t)D3];
__device__ __half g_wo16[D*(size_t)D];
__device__ __half g_w116[D*(size_t)FF];
__device__ __half g_w216[FF*(size_t)D];

// ---------------- helpers --------------------------------------------------
__device__ __forceinline__ unsigned smem_u32(const void* p) {
    return (unsigned)__cvta_generic_to_shared(p);
}
__device__ __forceinline__ void ldsm_x4(unsigned r[4], unsigned addr) {
    asm volatile("ldmatrix.sync.aligned.m8n8.x4.shared.b16 {%0,%1,%2,%3}, [%4];"
                 : "=r"(r[0]), "=r"(r[1]), "=r"(r[2]), "=r"(r[3]) : "r"(addr));
}
__device__ __forceinline__ void ldsm_x4t(unsigned r[4], unsigned addr) {
    asm volatile("ldmatrix.sync.aligned.m8n8.x4.trans.shared.b16 {%0,%1,%2,%3}, [%4];"
                 : "=r"(r[0]), "=r"(r[1]), "=r"(r[2]), "=r"(r[3]) : "r"(addr));
}
__device__ __forceinline__ void mma_f16(float c[4], const unsigned a[4], const unsigned b[2]) {
    asm volatile("mma.sync.aligned.m16n8k16.row.col.f32.f16.f16.f32 "
                 "{%0,%1,%2,%3}, {%4,%5,%6,%7}, {%8,%9}, {%0,%1,%2,%3};"
                 : "+f"(c[0]), "+f"(c[1]), "+f"(c[2]), "+f"(c[3])
                 : "r"(a[0]), "r"(a[1]), "r"(a[2]), "r"(a[3]), "r"(b[0]), "r"(b[1]));
}
__device__ __forceinline__ void cp16(unsigned dst, const void* src) {
    asm volatile("cp.async.cg.shared.global [%0], [%1], 16;" :: "r"(dst), "l"(src) : "memory");
}
__device__ __forceinline__ void cp_commit() { asm volatile("cp.async.commit_group;" ::: "memory"); }
template <int N>
__device__ __forceinline__ void cp_wait() { asm volatile("cp.async.wait_group %0;" :: "n"(N) : "memory"); }

// ==================== persistent fp16 GEMM v2 ================================
// 128x128 block tile, 64x32 warp tile, BK=64, 3-stage ring kept full across
// tile boundaries. Incremental load cursor: div/mod once per TILE only.
#define ASTR 72
#define BSTR 136
#define GEMM_GRID 296
struct GSmem {
    __half Ah[3][128][ASTR];
    __half Bh[3][64][BSTR];
};

// EPI: 0 = fp32 C; 1 = GELU then fp16; 2 = fp16
template <int EPI>
__global__ __launch_bounds__(256, 2) void gemm_f16(
    const __half* __restrict__ Ag, const __half* __restrict__ Bg,
    const float* __restrict__ bias,
    float* __restrict__ C, __half* __restrict__ Ch,
    int M, int N, int K)
{
    extern __shared__ char smem_raw[];
    GSmem& sm = *reinterpret_cast<GSmem*>(smem_raw);

    const int tid  = threadIdx.x;
    const int lane = tid & 31;
    const int wid  = tid >> 5;
    const int warpM = wid & 1;
    const int warpN = wid >> 1;
    const int bid  = blockIdx.x;
    const int nbx  = N >> 7;
    const int tiles = (M >> 7) * nbx;
    const int KT = K / 64;

    if (bid >= tiles) return;
    const int totLoads = ((tiles - bid - 1) / GEMM_GRID + 1) * KT;

    // ---- load cursor (incremental; div/mod once per tile) ----
    int ld_bx = bid % nbx, ld_by = bid / nbx, ld_kt = 0, ld_st = 0;
    int loadsIssued = 0;

    auto issue_load = [&]() {
        const int st = ld_st;
        #pragma unroll
        for (int q = 0; q < 4; q++) {
            int f = tid + q * 256;
            int r = f >> 3, c = (f & 7) * 8;
            cp16(smem_u32(&sm.Ah[st][r][c]),
                 Ag + (size_t)(ld_by * 128 + r) * K + ld_kt * 64 + c);
        }
        #pragma unroll
        for (int q = 0; q < 4; q++) {
            int f = tid + q * 256;
            int r = f >> 4, c = (f & 15) * 8;
            cp16(smem_u32(&sm.Bh[st][r][c]),
                 Bg + (size_t)(ld_kt * 64 + r) * N + ld_bx * 128 + c);
        }
        cp_commit();
        ld_st = (ld_st == 2) ? 0 : ld_st + 1;
        if (++ld_kt == KT) {
            ld_kt = 0;
            int nt = ld_by * nbx + ld_bx + GEMM_GRID;
            ld_bx = nt % nbx;
            ld_by = nt / nbx;
        }
        loadsIssued++;
    };

    issue_load();
    if (totLoads > 1) issue_load();

    const int arow = warpM * 64 + (lane & 15);
    const int acol8 = (lane >> 4) * 8;
    const int brow = ((lane >> 3) & 1) * 8 + (lane & 7);
    const int bcol = warpN * 32 + ((lane >> 4) & 1) * 8;
    const int g  = lane >> 2;
    const int t2 = (lane & 3) * 2;

    float acc[4][4][4];
    #pragma unroll
    for (int i = 0; i < 4; i++)
        #pragma unroll
        for (int j = 0; j < 4; j++)
            #pragma unroll
            for (int r = 0; r < 4; r++) acc[i][j][r] = 0.f;

    int st = 0;
    int consumed = 0;

    for (int tile = bid; tile < tiles; tile += GEMM_GRID) {
        const int bx = tile % nbx;
        const int by = tile / nbx;

        for (int kt = 0; kt < KT; kt++) {
            if (consumed + 1 < totLoads) cp_wait<1>(); else cp_wait<0>();
            __syncthreads();
            if (loadsIssued < totLoads) issue_load();

            #pragma unroll
            for (int ks = 0; ks < 4; ks++) {
                const int k0 = ks * 16;
                unsigned ah[4][4];
                #pragma unroll
                for (int mi = 0; mi < 4; mi++)
                    ldsm_x4(ah[mi], smem_u32(&sm.Ah[st][arow + mi * 16][k0 + acol8]));
                #pragma unroll
                for (int nn = 0; nn < 2; nn++) {
                    unsigned bh[4];
                    ldsm_x4t(bh, smem_u32(&sm.Bh[st][k0 + brow][bcol + nn * 16]));
                    #pragma unroll
                    for (int mi = 0; mi < 4; mi++) {
                        mma_f16(acc[mi][2*nn],   ah[mi], bh);
                        mma_f16(acc[mi][2*nn+1], ah[mi], bh + 2);
                    }
                }
            }
            st = (st == 2) ? 0 : st + 1;
            consumed++;
        }

        // ---- epilogue for this tile (next tile's loads already in flight) ----
        #pragma unroll
        for (int mi = 0; mi < 4; mi++) {
            #pragma unroll
            for (int ni = 0; ni < 4; ni++) {
                int row0 = by * 128 + warpM * 64 + mi * 16 + g;
                int col  = bx * 128 + warpN * 32 + ni * 8 + t2;
                float b0 = bias[col], b1 = bias[col + 1];
                #pragma unroll
                for (int half = 0; half < 2; half++) {
                    int row = row0 + half * 8;
                    float v0 = acc[mi][ni][half * 2 + 0] + b0;
                    float v1 = acc[mi][ni][half * 2 + 1] + b1;
                    if (EPI >= 1) {
                        if (EPI == 1) {
                            v0 = 0.5f * v0 * (1.f + erff(v0 * 0.70710678118654752f));
                            v1 = 0.5f * v1 * (1.f + erff(v1 * 0.70710678118654752f));
                        }
                        *(__half2*)(Ch + (size_t)row * N + col) = __floats2half2_rn(v0, v1);
                    } else {
                        float2 o; o.x = v0; o.y = v1;
                        *(float2*)(C + (size_t)row * N + col) = o;
                    }
                    acc[mi][ni][half * 2 + 0] = 0.f;
                    acc[mi][ni][half * 2 + 1] = 0.f;
                }
            }
        }
    }
}

// ---------------- merged fp32 -> fp16 conversion + bias concat --------------
__global__ __launch_bounds__(256) void convert_all(
    const float* __restrict__ x,  const float* __restrict__ Wq,
    const float* __restrict__ Wk, const float* __restrict__ Wv,
    const float* __restrict__ Wo, const float* __restrict__ W1,
    const float* __restrict__ W2,
    const float* __restrict__ bq, const float* __restrict__ bk,
    const float* __restrict__ bv,
    __half* __restrict__ x16, __half* __restrict__ wqkv,
    __half* __restrict__ wo,  __half* __restrict__ w1, __half* __restrict__ w2,
    float* __restrict__ bqkv)
{
    const int bid = blockIdx.x;
    const int tid = threadIdx.x;

    if (bid >= 32768) {
        int i = (bid - 32768) * 512 + tid * 2;
        if (i < D3) {
            int seg = i >> 10, off = i & (D - 1);
            const float* s = (seg == 0) ? bq : (seg == 1) ? bk : bv;
            bqkv[i]     = s[off];
            bqkv[i + 1] = s[off + 1];
        }
        return;
    }

    const float* src;
    __half* dst;
    int base;
    int qkvOff = -1;
    if (bid < 8192)       { src = x;  dst = x16; base = bid; }
    else if (bid < 10240) { src = Wq; dst = wqkv; base = bid - 8192;  qkvOff = 0; }
    else if (bid < 12288) { src = Wk; dst = wqkv; base = bid - 10240; qkvOff = D; }
    else if (bid < 14336) { src = Wv; dst = wqkv; base = bid - 12288; qkvOff = 2 * D; }
    else if (bid < 16384) { src = Wo; dst = wo;  base = bid - 14336; }
    else if (bid < 24576) { src = W1; dst = w1;  base = bid - 16384; }
    else                  { src = W2; dst = w2;  base = bid - 24576; }

    int i = (base * 256 + tid) * 2;
    float2 v = *(const float2*)(src + i);
    __half2 hv = __floats2half2_rn(v.x, v.y);
    if (qkvOff >= 0) {
        int r = i >> 10;
        int c = i & (D - 1);
        *(__half2*)(dst + (size_t)r * D3 + qkvOff + c) = hv;
    } else {
        *(__half2*)(dst + i) = hv;
    }
}

// ==================== fp16 mma flash attention (R13) =========================
#define QPAD 72
struct AttnSmem {
    __half Qh[128][QPAD];
    __half Kh[3][64][QPAD];
    __half Vh[3][64][QPAD];
};

__global__ __launch_bounds__(256, 2) void attn_mma(
    const __half* __restrict__ qg, const __half* __restrict__ kg,
    const __half* __restrict__ vg, __half* __restrict__ ctx, int ld)
{
    extern __shared__ char smem_raw[];
    AttnSmem& sm = *reinterpret_cast<AttnSmem*>(smem_raw);

    const int tid  = threadIdx.x;
    const int lane = tid & 31;
    const int w    = tid >> 5;
    const int g    = lane >> 2;
    const int t    = lane & 3;

    const int qt = (int)gridDim.x - 1 - (int)blockIdx.x;
    const int h  = blockIdx.y;
    const int b  = blockIdx.z;
    const size_t q0 = (size_t)b * SEQ + qt * 128;
    const int hcol = h * HD;
    const float SC = 0.125f * 1.44269504088896340736f;

    #pragma unroll
    for (int l = 0; l < 4; l++) {
        int f = tid + l * 256;
        int r = f >> 3, c = (f & 7) * 8;
        cp16(smem_u32(&sm.Qh[r][c]), qg + (q0 + r) * ld + hcol + c);
    }

    auto load_kv = [&](int st, int kt) {
        const size_t kr0 = (size_t)b * SEQ + kt * 64;
        #pragma unroll
        for (int l = 0; l < 2; l++) {
            int f = tid + l * 256;
            int r = f >> 3, c = (f & 7) * 8;
            const size_t go = (kr0 + r) * ld + hcol + c;
            cp16(smem_u32(&sm.Kh[st][r][c]), kg + go);
            cp16(smem_u32(&sm.Vh[st][r][c]), vg + go);
        }
    };

    const int ktiles = qt * 2 + 2;
    load_kv(0, 0); cp_commit();
    load_kv(1, 1); cp_commit();

    const int qbase = qt * 128 + w * 16;
    const int qmax  = qbase + 15;

    const int krow_lo = (lane & 7) + ((lane >> 4) & 1) * 8;
    const int kcol8   = ((lane >> 3) & 1) * 8;
    const int vrow    = lane & 15;
    const int vcol8   = ((lane >> 4) & 1) * 8;

    unsigned qf[4][4];
    float m[2] = {-1e30f, -1e30f};
    float lsum[2] = {0.f, 0.f};
    float acc[8][4];
    #pragma unroll
    for (int nf = 0; nf < 8; nf++)
        #pragma unroll
        for (int i = 0; i < 4; i++) acc[nf][i] = 0.f;

    const __half2 sch = __floats2half2_rn(SC, SC);

    for (int kt = 0; kt < ktiles; kt++) {
        const int st = kt % 3;
        if (kt + 1 >= ktiles) cp_wait<0>(); else cp_wait<1>();
        __syncthreads();
        if (kt + 2 < ktiles) { load_kv((kt + 2) % 3, kt + 2); cp_commit(); }

        if (kt == 0) {
            #pragma unroll
            for (int kf = 0; kf < 4; kf++) {
                int r = w * 16 + (lane & 15);
                int c = kf * 16 + (lane >> 4) * 8;
                ldsm_x4(qf[kf], smem_u32(&sm.Qh[r][c]));
                #pragma unroll
                for (int i = 0; i < 4; i++) {
                    __half2 qh2 = __hmul2(*(__half2*)&qf[kf][i], sch);
                    qf[kf][i] = *(unsigned*)&qh2;
                }
            }
        }

        const int kbase = kt * 64;
        if (kbase > qmax) continue;

        float s[8][4];
        #pragma unroll
        for (int nf = 0; nf < 8; nf++)
            #pragma unroll
            for (int i = 0; i < 4; i++) s[nf][i] = 0.f;

        #pragma unroll
        for (int nf2 = 0; nf2 < 4; nf2++) {
            #pragma unroll
            for (int kf = 0; kf < 4; kf++) {
                unsigned kb[4];
                int kr = nf2 * 16 + krow_lo;
                int kc = kf * 16 + kcol8;
                ldsm_x4(kb, smem_u32(&sm.Kh[st][kr][kc]));
                mma_f16(s[2*nf2],     qf[kf], kb);
                mma_f16(s[2*nf2 + 1], qf[kf], kb + 2);
            }
        }

        if (kbase + 63 > qbase) {
            #pragma unroll
            for (int nf = 0; nf < 8; nf++) {
                #pragma unroll
                for (int i = 0; i < 4; i++) {
                    int key = kbase + nf * 8 + 2 * t + (i & 1);
                    int qry = qbase + g + (i >> 1) * 8;
                    s[nf][i] = (key > qry) ? -1e30f : s[nf][i];
                }
            }
        }

        float cfac[2];
        unsigned ph[4][4];
        #pragma unroll
        for (int r = 0; r < 2; r++) {
            float vmax = -1e30f;
            #pragma unroll
            for (int nf = 0; nf < 8; nf++) {
                vmax = fmaxf(vmax, s[nf][2 * r]);
                vmax = fmaxf(vmax, s[nf][2 * r + 1]);
            }
            vmax = fmaxf(vmax, __shfl_xor_sync(0xffffffffu, vmax, 1));
            vmax = fmaxf(vmax, __shfl_xor_sync(0xffffffffu, vmax, 2));
            float mn = fmaxf(m[r], vmax);
            cfac[r] = exp2f(m[r] - mn);
            m[r] = mn;
            float rowsum = 0.f;
            #pragma unroll
            for (int nf = 0; nf < 8; nf++) {
                __half2 hd = __floats2half2_rn(s[nf][2 * r] - mn, s[nf][2 * r + 1] - mn);
                unsigned e;
                asm("ex2.approx.f16x2 %0, %1;" : "=r"(e) : "r"(*(unsigned*)&hd));
                ph[nf >> 1][(nf & 1) * 2 + r] = e;
                float2 pf = __half22float2(*(__half2*)&e);
                rowsum += pf.x + pf.y;
            }
            rowsum += __shfl_xor_sync(0xffffffffu, rowsum, 1);
            rowsum += __shfl_xor_sync(0xffffffffu, rowsum, 2);
            lsum[r] = lsum[r] * cfac[r] + rowsum;
        }
        #pragma unroll
        for (int nf = 0; nf < 8; nf++) {
            acc[nf][0] *= cfac[0]; acc[nf][1] *= cfac[0];
            acc[nf][2] *= cfac[1]; acc[nf][3] *= cfac[1];
        }

        #pragma unroll
        for (int nf2 = 0; nf2 < 4; nf2++) {
            #pragma unroll
            for (int kf = 0; kf < 4; kf++) {
                unsigned vb[4];
                int vr = kf * 16 + vrow;
                int vc = nf2 * 16 + vcol8;
                ldsm_x4t(vb, smem_u32(&sm.Vh[st][vr][vc]));
                mma_f16(acc[2*nf2],     ph[kf], vb);
                mma_f16(acc[2*nf2 + 1], ph[kf], vb + 2);
            }
        }
    }

    const float inv0 = 1.f / lsum[0];
    const float inv1 = 1.f / lsum[1];
    #pragma unroll
    for (int nf = 0; nf < 8; nf++) {
        int col = hcol + nf * 8 + 2 * t;
        size_t row0 = q0 + w * 16 + g;
        *(__half2*)(ctx + row0 * D + col)       = __floats2half2_rn(acc[nf][0] * inv0, acc[nf][1] * inv0);
        *(__half2*)(ctx + (row0 + 8) * D + col) = __floats2half2_rn(acc[nf][2] * inv1, acc[nf][3] * inv1);
    }
}

// ---------------- fused residual add + LayerNorm (float4 I/O) ---------------
template <int WB>
__global__ __launch_bounds__(256) void add_ln(
    const float* __restrict__ Ain, const float* __restrict__ Bin,
    const float* __restrict__ g, const float* __restrict__ be,
    float* __restrict__ out, __half* __restrict__ oh)
{
    const int row = blockIdx.x;
    const int tid = threadIdx.x;
    const float* a = Ain + (size_t)row * D;
    const float* b = Bin + (size_t)row * D;

    float4 va = *(const float4*)(a + tid * 4);
    float4 vb = *(const float4*)(b + tid * 4);
    float v0 = va.x + vb.x, v1 = va.y + vb.y, v2 = va.z + vb.z, v3 = va.w + vb.w;

    float s  = v0 + v1 + v2 + v3;
    float s2 = v0*v0 + v1*v1 + v2*v2 + v3*v3;
    #pragma unroll
    for (int off = 16; off > 0; off >>= 1) {
        s  += __shfl_xor_sync(0xffffffffu, s,  off);
        s2 += __shfl_xor_sync(0xffffffffu, s2, off);
    }
    __shared__ float sh[2][8];
    if ((tid & 31) == 0) { sh[0][tid >> 5] = s; sh[1][tid >> 5] = s2; }
    __syncthreads();
    float ts = 0.f, t2 = 0.f;
    #pragma unroll
    for (int w = 0; w < 8; w++) { ts += sh[0][w]; t2 += sh[1][w]; }

    const float mu  = ts * (1.f / D);
    const float var = t2 * (1.f / D) - mu * mu;
    const float inv = rsqrtf(var + 1e-5f);

    float4 gg = *(const float4*)(g + tid * 4);
    float4 bb = *(const float4*)(be + tid * 4);
    float o0 = (v0 - mu) * inv * gg.x + bb.x;
    float o1 = (v1 - mu) * inv * gg.y + bb.y;
    float o2 = (v2 - mu) * inv * gg.z + bb.z;
    float o3 = (v3 - mu) * inv * gg.w + bb.w;

    float4 ov; ov.x = o0; ov.y = o1; ov.z = o2; ov.w = o3;
    *(float4*)(out + (size_t)row * D + tid * 4) = ov;
    if (WB) {
        *(__half2*)(oh + (size_t)row * D + tid * 4)     = __floats2half2_rn(o0, o1);
        *(__half2*)(oh + (size_t)row * D + tid * 4 + 2) = __floats2half2_rn(o2, o3);
    }
}

// ---------------- launch -----------------------------------------------------
extern "C" void kernel_launch(void* const* d_in, const int* in_sizes, int n_in,
                              void* d_out, int out_size)
{
    const float* x    = (const float*)d_in[0];
    const float* Wq   = (const float*)d_in[1];
    const float* bq   = (const float*)d_in[2];
    const float* Wk   = (const float*)d_in[3];
    const float* bk   = (const float*)d_in[4];
    const float* Wv   = (const float*)d_in[5];
    const float* bv   = (const float*)d_in[6];
    const float* Wo   = (const float*)d_in[7];
    const float* bo   = (const float*)d_in[8];
    const float* ln1g = (const float*)d_in[9];
    const float* ln1b = (const float*)d_in[10];
    const float* W1   = (const float*)d_in[11];
    const float* b1   = (const float*)d_in[12];
    const float* W2   = (const float*)d_in[13];
    const float* b2   = (const float*)d_in[14];
    const float* ln2g = (const float*)d_in[15];
    const float* ln2b = (const float*)d_in[16];
    float* out = (float*)d_out;

    float *attnres, *h, *ff2, *bqkv;
    cudaGetSymbolAddress((void**)&attnres, g_attnres);
    cudaGetSymbolAddress((void**)&h,    g_h);
    cudaGetSymbolAddress((void**)&ff2,  g_ff2);
    cudaGetSymbolAddress((void**)&bqkv, g_bqkv);

    __half *x16,*qkv16,*ctx16,*h16,*f116,*wqkv16,*wo16,*w116,*w216;
    cudaGetSymbolAddress((void**)&x16,   g_x16);
    cudaGetSymbolAddress((void**)&qkv16, g_qkv16);
    cudaGetSymbolAddress((void**)&ctx16, g_ctx16);
    cudaGetSymbolAddress((void**)&h16,   g_h16);
    cudaGetSymbolAddress((void**)&f116,  g_f116);
    cudaGetSymbolAddress((void**)&wqkv16,g_wqkv16);
    cudaGetSymbolAddress((void**)&wo16,  g_wo16);
    cudaGetSymbolAddress((void**)&w116,  g_w116);
    cudaGetSymbolAddress((void**)&w216,  g_w216);

    static int attr_set = 0;
    if (!attr_set) {
        cudaFuncSetAttribute(gemm_f16<0>, cudaFuncAttributeMaxDynamicSharedMemorySize, (int)sizeof(GSmem));
        cudaFuncSetAttribute(gemm_f16<1>, cudaFuncAttributeMaxDynamicSharedMemorySize, (int)sizeof(GSmem));
        cudaFuncSetAttribute(gemm_f16<2>, cudaFuncAttributeMaxDynamicSharedMemorySize, (int)sizeof(GSmem));
        cudaFuncSetAttribute(attn_mma, cudaFuncAttributeMaxDynamicSharedMemorySize, (int)sizeof(AttnSmem));
        attr_set = 1;
    }
    const int SG = (int)sizeof(GSmem);
    const int SA = (int)sizeof(AttnSmem);

    // ---- conversions + bias concat ----
    convert_all<<<32774, 256>>>(x, Wq, Wk, Wv, Wo, W1, W2, bq, bk, bv,
                                x16, wqkv16, wo16, w116, w216, bqkv);

    // ---- merged QKV projection (persistent: 768 tiles over 296 CTAs) ----
    gemm_f16<2><<<GEMM_GRID, 256, SG>>>(x16, wqkv16, bqkv, nullptr, qkv16, MTOK, D3, D);

    // ---- flash attention ----
    dim3 gAttn(SEQ / 128, NH, BATCH);
    attn_mma<<<gAttn, 256, SA>>>(qkv16, qkv16 + D, qkv16 + 2*D, ctx16, D3);

    // ---- O projection (256 tiles -> 256 CTAs, single pass) ----
    gemm_f16<0><<<256, 256, SG>>>(ctx16, wo16, bo, attnres, nullptr, MTOK, D, D);

    // ---- LN1 ----
    add_ln<1><<<MTOK, 256>>>(attnres, x, ln1g, ln1b, h, h16);

    // ---- FFN ----
    gemm_f16<1><<<GEMM_GRID, 256, SG>>>(h16, w116, b1, nullptr, f116, MTOK, FF, D);
    gemm_f16<0><<<256, 256, SG>>>(f116, w216, b2, ff2, nullptr, MTOK, D, FF);

    // ---- LN2 ----
    add_ln<0><<<MTOK, 256>>>(ff2, h, ln2g, ln2b, out, nullptr);
}

// round 16
// speedup vs baseline: 1.1095x; 1.0584x over previous
#include <cuda_runtime.h>
#include <cuda_fp16.h>
#include <stdint.h>
#include <math.h>

#define D     1024
#define NH    16
#define HD    64
#define FF    4096
#define SEQ   2048
#define BATCH 2
#define MTOK  (BATCH*SEQ)   // 4096 rows
#define D3    (3*D)

// ---------------- scratch (static device globals; no allocs) ----------------
__device__ float g_attnres[MTOK*(size_t)D];
__device__ float g_h[MTOK*(size_t)D];
__device__ float g_ff2[MTOK*(size_t)D];
__device__ float g_bqkv[D3];

__device__ __half g_x16[MTOK*(size_t)D];
__device__ __half g_qkv16[MTOK*(size_t)D3];
__device__ __half g_ctx16[MTOK*(size_t)D];
__device__ __half g_h16[MTOK*(size_t)D];
__device__ __half g_f116[MTOK*(size_t)FF];
__device__ __half g_wqkv16[D*(size_t)D3];
__device__ __half g_wo16[D*(size_t)D];
__device__ __half g_w116[D*(size_t)FF];
__device__ __half g_w216[FF*(size_t)D];

// ---------------- helpers --------------------------------------------------
__device__ __forceinline__ unsigned smem_u32(const void* p) {
    return (unsigned)__cvta_generic_to_shared(p);
}
__device__ __forceinline__ void ldsm_x4(unsigned r[4], unsigned addr) {
    asm volatile("ldmatrix.sync.aligned.m8n8.x4.shared.b16 {%0,%1,%2,%3}, [%4];"
                 : "=r"(r[0]), "=r"(r[1]), "=r"(r[2]), "=r"(r[3]) : "r"(addr));
}
__device__ __forceinline__ void ldsm_x4t(unsigned r[4], unsigned addr) {
    asm volatile("ldmatrix.sync.aligned.m8n8.x4.trans.shared.b16 {%0,%1,%2,%3}, [%4];"
                 : "=r"(r[0]), "=r"(r[1]), "=r"(r[2]), "=r"(r[3]) : "r"(addr));
}
__device__ __forceinline__ void mma_f16(float c[4], const unsigned a[4], const unsigned b[2]) {
    asm volatile("mma.sync.aligned.m16n8k16.row.col.f32.f16.f16.f32 "
                 "{%0,%1,%2,%3}, {%4,%5,%6,%7}, {%8,%9}, {%0,%1,%2,%3};"
                 : "+f"(c[0]), "+f"(c[1]), "+f"(c[2]), "+f"(c[3])
                 : "r"(a[0]), "r"(a[1]), "r"(a[2]), "r"(a[3]), "r"(b[0]), "r"(b[1]));
}
__device__ __forceinline__ void cp16(unsigned dst, const void* src) {
    asm volatile("cp.async.cg.shared.global [%0], [%1], 16;" :: "r"(dst), "l"(src) : "memory");
}
__device__ __forceinline__ void cp_commit() { asm volatile("cp.async.commit_group;" ::: "memory"); }
template <int N>
__device__ __forceinline__ void cp_wait() { asm volatile("cp.async.wait_group %0;" :: "n"(N) : "memory"); }

// ==================== fp16 GEMM: 128x128 block, 64x32 warp, BK=64 ==========
// (R13 config: classic per-tile grid, occ 2, 3-stage ring)
#define ASTR 72
#define BSTR 136
struct GSmem {
    __half Ah[3][128][ASTR];
    __half Bh[3][64][BSTR];
};

// EPI: 0 = fp32 C; 1 = GELU then fp16; 2 = fp16
template <int EPI>
__global__ __launch_bounds__(256, 2) void gemm_f16(
    const __half* __restrict__ Ag, const __half* __restrict__ Bg,
    const float* __restrict__ bias,
    float* __restrict__ C, __half* __restrict__ Ch,
    int M, int N, int K)
{
    extern __shared__ char smem_raw[];
    GSmem& sm = *reinterpret_cast<GSmem*>(smem_raw);

    const int tid  = threadIdx.x;
    const int lane = tid & 31;
    const int wid  = tid >> 5;
    const int warpM = wid & 1;
    const int warpN = wid >> 1;
    const int bx = blockIdx.x;
    const int by = blockIdx.y;
    const int KT = K / 64;

    float acc[4][4][4];
    #pragma unroll
    for (int i = 0; i < 4; i++)
        #pragma unroll
        for (int j = 0; j < 4; j++)
            #pragma unroll
            for (int r = 0; r < 4; r++) acc[i][j][r] = 0.f;

    auto load_stage = [&](int st, int kt) {
        #pragma unroll
        for (int l = 0; l < 4; l++) {
            int f = tid + l * 256;
            int r = f >> 3, c = (f & 7) * 8;
            cp16(smem_u32(&sm.Ah[st][r][c]), Ag + (size_t)(by * 128 + r) * K + kt * 64 + c);
        }
        #pragma unroll
        for (int l = 0; l < 4; l++) {
            int f = tid + l * 256;
            int r = f >> 4, c = (f & 15) * 8;
            cp16(smem_u32(&sm.Bh[st][r][c]), Bg + (size_t)(kt * 64 + r) * N + bx * 128 + c);
        }
    };

    load_stage(0, 0); cp_commit();
    load_stage(1, 1); cp_commit();

    const int arow = warpM * 64 + (lane & 15);
    const int acol8 = (lane >> 4) * 8;
    const int brow = ((lane >> 3) & 1) * 8 + (lane & 7);
    const int bcol = warpN * 32 + ((lane >> 4) & 1) * 8;

    for (int kt = 0; kt < KT; kt++) {
        const int st = kt % 3;
        if (kt == KT - 1) cp_wait<0>(); else cp_wait<1>();
        __syncthreads();
        if (kt + 2 < KT) { load_stage((kt + 2) % 3, kt + 2); cp_commit(); }

        #pragma unroll
        for (int ks = 0; ks < 4; ks++) {
            const int k0 = ks * 16;
            unsigned ah[4][4];
            #pragma unroll
            for (int mi = 0; mi < 4; mi++)
                ldsm_x4(ah[mi], smem_u32(&sm.Ah[st][arow + mi * 16][k0 + acol8]));
            #pragma unroll
            for (int nn = 0; nn < 2; nn++) {
                unsigned bh[4];
                ldsm_x4t(bh, smem_u32(&sm.Bh[st][k0 + brow][bcol + nn * 16]));
                #pragma unroll
                for (int mi = 0; mi < 4; mi++) {
                    mma_f16(acc[mi][2*nn],   ah[mi], bh);
                    mma_f16(acc[mi][2*nn+1], ah[mi], bh + 2);
                }
            }
        }
    }

    const int g  = lane >> 2;
    const int t2 = (lane & 3) * 2;
    #pragma unroll
    for (int mi = 0; mi < 4; mi++) {
        #pragma unroll
        for (int ni = 0; ni < 4; ni++) {
            int row0 = by * 128 + warpM * 64 + mi * 16 + g;
            int col  = bx * 128 + warpN * 32 + ni * 8 + t2;
            float b0 = bias[col], b1 = bias[col + 1];
            #pragma unroll
            for (int half = 0; half < 2; half++) {
                int row = row0 + half * 8;
                float v0 = acc[mi][ni][half * 2 + 0] + b0;
                float v1 = acc[mi][ni][half * 2 + 1] + b1;
                if (EPI >= 1) {
                    if (EPI == 1) {
                        v0 = 0.5f * v0 * (1.f + erff(v0 * 0.70710678118654752f));
                        v1 = 0.5f * v1 * (1.f + erff(v1 * 0.70710678118654752f));
                    }
                    *(__half2*)(Ch + (size_t)row * N + col) = __floats2half2_rn(v0, v1);
                } else {
                    float2 o; o.x = v0; o.y = v1;
                    *(float2*)(C + (size_t)row * N + col) = o;
                }
            }
        }
    }
}

// ---------------- merged fp32 -> fp16 conversion + bias concat --------------
// 8 elements per thread (2x float4 load, 1x 16B store) for DRAM saturation.
// Block regions (each block = 2048 elems): x:[0,2048) Wq:[2048,2560)
// Wk:[2560,3072) Wv:[3072,3584) Wo:[3584,4096) W1:[4096,6144) W2:[6144,8192)
// bias concat: [8192,8198)
__global__ __launch_bounds__(256) void convert_all(
    const float* __restrict__ x,  const float* __restrict__ Wq,
    const float* __restrict__ Wk, const float* __restrict__ Wv,
    const float* __restrict__ Wo, const float* __restrict__ W1,
    const float* __restrict__ W2,
    const float* __restrict__ bq, const float* __restrict__ bk,
    const float* __restrict__ bv,
    __half* __restrict__ x16, __half* __restrict__ wqkv,
    __half* __restrict__ wo,  __half* __restrict__ w1, __half* __restrict__ w2,
    float* __restrict__ bqkv)
{
    const int bid = blockIdx.x;
    const int tid = threadIdx.x;

    if (bid >= 8192) {                       // bias concat region: 6 blocks
        int i = (bid - 8192) * 512 + tid * 2;
        if (i < D3) {
            int seg = i >> 10, off = i & (D - 1);
            const float* s = (seg == 0) ? bq : (seg == 1) ? bk : bv;
            bqkv[i]     = s[off];
            bqkv[i + 1] = s[off + 1];
        }
        return;
    }

    const float* src;
    __half* dst;
    int base;
    int qkvOff = -1;
    if (bid < 2048)      { src = x;  dst = x16; base = bid; }
    else if (bid < 2560) { src = Wq; dst = wqkv; base = bid - 2048; qkvOff = 0; }
    else if (bid < 3072) { src = Wk; dst = wqkv; base = bid - 2560; qkvOff = D; }
    else if (bid < 3584) { src = Wv; dst = wqkv; base = bid - 3072; qkvOff = 2 * D; }
    else if (bid < 4096) { src = Wo; dst = wo;  base = bid - 3584; }
    else if (bid < 6144) { src = W1; dst = w1;  base = bid - 4096; }
    else                 { src = W2; dst = w2;  base = bid - 6144; }

    int i = (base * 256 + tid) * 8;
    float4 v0 = *(const float4*)(src + i);
    float4 v1 = *(const float4*)(src + i + 4);
    __half2 h0 = __floats2half2_rn(v0.x, v0.y);
    __half2 h1 = __floats2half2_rn(v0.z, v0.w);
    __half2 h2 = __floats2half2_rn(v1.x, v1.y);
    __half2 h3 = __floats2half2_rn(v1.z, v1.w);
    uint4 packed;
    packed.x = *(unsigned*)&h0; packed.y = *(unsigned*)&h1;
    packed.z = *(unsigned*)&h2; packed.w = *(unsigned*)&h3;

    if (qkvOff >= 0) {
        int r = i >> 10;
        int c = i & (D - 1);
        *(uint4*)(dst + (size_t)r * D3 + qkvOff + c) = packed;
    } else {
        *(uint4*)(dst + i) = packed;
    }
}

// ==================== fp16 mma flash attention (R13) =========================
#define QPAD 72
struct AttnSmem {
    __half Qh[128][QPAD];
    __half Kh[3][64][QPAD];
    __half Vh[3][64][QPAD];
};

__global__ __launch_bounds__(256, 2) void attn_mma(
    const __half* __restrict__ qg, const __half* __restrict__ kg,
    const __half* __restrict__ vg, __half* __restrict__ ctx, int ld)
{
    extern __shared__ char smem_raw[];
    AttnSmem& sm = *reinterpret_cast<AttnSmem*>(smem_raw);

    const int tid  = threadIdx.x;
    const int lane = tid & 31;
    const int w    = tid >> 5;
    const int g    = lane >> 2;
    const int t    = lane & 3;

    const int qt = (int)gridDim.x - 1 - (int)blockIdx.x;
    const int h  = blockIdx.y;
    const int b  = blockIdx.z;
    const size_t q0 = (size_t)b * SEQ + qt * 128;
    const int hcol = h * HD;
    const float SC = 0.125f * 1.44269504088896340736f;

    #pragma unroll
    for (int l = 0; l < 4; l++) {
        int f = tid + l * 256;
        int r = f >> 3, c = (f & 7) * 8;
        cp16(smem_u32(&sm.Qh[r][c]), qg + (q0 + r) * ld + hcol + c);
    }

    auto load_kv = [&](int st, int kt) {
        const size_t kr0 = (size_t)b * SEQ + kt * 64;
        #pragma unroll
        for (int l = 0; l < 2; l++) {
            int f = tid + l * 256;
            int r = f >> 3, c = (f & 7) * 8;
            const size_t go = (kr0 + r) * ld + hcol + c;
            cp16(smem_u32(&sm.Kh[st][r][c]), kg + go);
            cp16(smem_u32(&sm.Vh[st][r][c]), vg + go);
        }
    };

    const int ktiles = qt * 2 + 2;
    load_kv(0, 0); cp_commit();
    load_kv(1, 1); cp_commit();

    const int qbase = qt * 128 + w * 16;
    const int qmax  = qbase + 15;

    const int krow_lo = (lane & 7) + ((lane >> 4) & 1) * 8;
    const int kcol8   = ((lane >> 3) & 1) * 8;
    const int vrow    = lane & 15;
    const int vcol8   = ((lane >> 4) & 1) * 8;

    unsigned qf[4][4];
    float m[2] = {-1e30f, -1e30f};
    float lsum[2] = {0.f, 0.f};
    float acc[8][4];
    #pragma unroll
    for (int nf = 0; nf < 8; nf++)
        #pragma unroll
        for (int i = 0; i < 4; i++) acc[nf][i] = 0.f;

    const __half2 sch = __floats2half2_rn(SC, SC);

    for (int kt = 0; kt < ktiles; kt++) {
        const int st = kt % 3;
        if (kt + 1 >= ktiles) cp_wait<0>(); else cp_wait<1>();
        __syncthreads();
        if (kt + 2 < ktiles) { load_kv((kt + 2) % 3, kt + 2); cp_commit(); }

        if (kt == 0) {
            #pragma unroll
            for (int kf = 0; kf < 4; kf++) {
                int r = w * 16 + (lane & 15);
                int c = kf * 16 + (lane >> 4) * 8;
                ldsm_x4(qf[kf], smem_u32(&sm.Qh[r][c]));
                #pragma unroll
                for (int i = 0; i < 4; i++) {
                    __half2 qh2 = __hmul2(*(__half2*)&qf[kf][i], sch);
                    qf[kf][i] = *(unsigned*)&qh2;
                }
            }
        }

        const int kbase = kt * 64;
        if (kbase > qmax) continue;

        float s[8][4];
        #pragma unroll
        for (int nf = 0; nf < 8; nf++)
            #pragma unroll
            for (int i = 0; i < 4; i++) s[nf][i] = 0.f;

        #pragma unroll
        for (int nf2 = 0; nf2 < 4; nf2++) {
            #pragma unroll
            for (int kf = 0; kf < 4; kf++) {
                unsigned kb[4];
                int kr = nf2 * 16 + krow_lo;
                int kc = kf * 16 + kcol8;
                ldsm_x4(kb, smem_u32(&sm.Kh[st][kr][kc]));
                mma_f16(s[2*nf2],     qf[kf], kb);
                mma_f16(s[2*nf2 + 1], qf[kf], kb + 2);
            }
        }

        if (kbase + 63 > qbase) {
            #pragma unroll
            for (int nf = 0; nf < 8; nf++) {
                #pragma unroll
                for (int i = 0; i < 4; i++) {
                    int key = kbase + nf * 8 + 2 * t + (i & 1);
                    int qry = qbase + g + (i >> 1) * 8;
                    s[nf][i] = (key > qry) ? -1e30f : s[nf][i];
                }
            }
        }

        float cfac[2];
        unsigned ph[4][4];
        #pragma unroll
        for (int r = 0; r < 2; r++) {
            float vmax = -1e30f;
            #pragma unroll
            for (int nf = 0; nf < 8; nf++) {
                vmax = fmaxf(vmax, s[nf][2 * r]);
                vmax = fmaxf(vmax, s[nf][2 * r + 1]);
            }
            vmax = fmaxf(vmax, __shfl_xor_sync(0xffffffffu, vmax, 1));
            vmax = fmaxf(vmax, __shfl_xor_sync(0xffffffffu, vmax, 2));
            float mn = fmaxf(m[r], vmax);
            cfac[r] = exp2f(m[r] - mn);
            m[r] = mn;
            float rowsum = 0.f;
            #pragma unroll
            for (int nf = 0; nf < 8; nf++) {
                __half2 hd = __floats2half2_rn(s[nf][2 * r] - mn, s[nf][2 * r + 1] - mn);
                unsigned e;
                asm("ex2.approx.f16x2 %0, %1;" : "=r"(e) : "r"(*(unsigned*)&hd));
                ph[nf >> 1][(nf & 1) * 2 + r] = e;
                float2 pf = __half22float2(*(__half2*)&e);
                rowsum += pf.x + pf.y;
            }
            rowsum += __shfl_xor_sync(0xffffffffu, rowsum, 1);
            rowsum += __shfl_xor_sync(0xffffffffu, rowsum, 2);
            lsum[r] = lsum[r] * cfac[r] + rowsum;
        }
        #pragma unroll
        for (int nf = 0; nf < 8; nf++) {
            acc[nf][0] *= cfac[0]; acc[nf][1] *= cfac[0];
            acc[nf][2] *= cfac[1]; acc[nf][3] *= cfac[1];
        }

        #pragma unroll
        for (int nf2 = 0; nf2 < 4; nf2++) {
            #pragma unroll
            for (int kf = 0; kf < 4; kf++) {
                unsigned vb[4];
                int vr = kf * 16 + vrow;
                int vc = nf2 * 16 + vcol8;
                ldsm_x4t(vb, smem_u32(&sm.Vh[st][vr][vc]));
                mma_f16(acc[2*nf2],     ph[kf], vb);
                mma_f16(acc[2*nf2 + 1], ph[kf], vb + 2);
            }
        }
    }

    const float inv0 = 1.f / lsum[0];
    const float inv1 = 1.f / lsum[1];
    #pragma unroll
    for (int nf = 0; nf < 8; nf++) {
        int col = hcol + nf * 8 + 2 * t;
        size_t row0 = q0 + w * 16 + g;
        *(__half2*)(ctx + row0 * D + col)       = __floats2half2_rn(acc[nf][0] * inv0, acc[nf][1] * inv0);
        *(__half2*)(ctx + (row0 + 8) * D + col) = __floats2half2_rn(acc[nf][2] * inv1, acc[nf][3] * inv1);
    }
}

// ---------------- fused residual add + LayerNorm (float4 I/O) ---------------
template <int WB>
__global__ __launch_bounds__(256) void add_ln(
    const float* __restrict__ Ain, const float* __restrict__ Bin,
    const float* __restrict__ g, const float* __restrict__ be,
    float* __restrict__ out, __half* __restrict__ oh)
{
    const int row = blockIdx.x;
    const int tid = threadIdx.x;
    const float* a = Ain + (size_t)row * D;
    const float* b = Bin + (size_t)row * D;

    float4 va = *(const float4*)(a + tid * 4);
    float4 vb = *(const float4*)(b + tid * 4);
    float v0 = va.x + vb.x, v1 = va.y + vb.y, v2 = va.z + vb.z, v3 = va.w + vb.w;

    float s  = v0 + v1 + v2 + v3;
    float s2 = v0*v0 + v1*v1 + v2*v2 + v3*v3;
    #pragma unroll
    for (int off = 16; off > 0; off >>= 1) {
        s  += __shfl_xor_sync(0xffffffffu, s,  off);
        s2 += __shfl_xor_sync(0xffffffffu, s2, off);
    }
    __shared__ float sh[2][8];
    if ((tid & 31) == 0) { sh[0][tid >> 5] = s; sh[1][tid >> 5] = s2; }
    __syncthreads();
    float ts = 0.f, t2 = 0.f;
    #pragma unroll
    for (int w = 0; w < 8; w++) { ts += sh[0][w]; t2 += sh[1][w]; }

    const float mu  = ts * (1.f / D);
    const float var = t2 * (1.f / D) - mu * mu;
    const float inv = rsqrtf(var + 1e-5f);

    float4 gg = *(const float4*)(g + tid * 4);
    float4 bb = *(const float4*)(be + tid * 4);
    float o0 = (v0 - mu) * inv * gg.x + bb.x;
    float o1 = (v1 - mu) * inv * gg.y + bb.y;
    float o2 = (v2 - mu) * inv * gg.z + bb.z;
    float o3 = (v3 - mu) * inv * gg.w + bb.w;

    float4 ov; ov.x = o0; ov.y = o1; ov.z = o2; ov.w = o3;
    *(float4*)(out + (size_t)row * D + tid * 4) = ov;
    if (WB) {
        *(__half2*)(oh + (size_t)row * D + tid * 4)     = __floats2half2_rn(o0, o1);
        *(__half2*)(oh + (size_t)row * D + tid * 4 + 2) = __floats2half2_rn(o2, o3);
    }
}

// ---------------- launch -----------------------------------------------------
extern "C" void kernel_launch(void* const* d_in, const int* in_sizes, int n_in,
                              void* d_out, int out_size)
{
    const float* x    = (const float*)d_in[0];
    const float* Wq   = (const float*)d_in[1];
    const float* bq   = (const float*)d_in[2];
    const float* Wk   = (const float*)d_in[3];
    const float* bk   = (const float*)d_in[4];
    const float* Wv   = (const float*)d_in[5];
    const float* bv   = (const float*)d_in[6];
    const float* Wo   = (const float*)d_in[7];
    const float* bo   = (const float*)d_in[8];
    const float* ln1g = (const float*)d_in[9];
    const float* ln1b = (const float*)d_in[10];
    const float* W1   = (const float*)d_in[11];
    const float* b1   = (const float*)d_in[12];
    const float* W2   = (const float*)d_in[13];
    const float* b2   = (const float*)d_in[14];
    const float* ln2g = (const float*)d_in[15];
    const float* ln2b = (const float*)d_in[16];
    float* out = (float*)d_out;

    float *attnres, *h, *ff2, *bqkv;
    cudaGetSymbolAddress((void**)&attnres, g_attnres);
    cudaGetSymbolAddress((void**)&h,    g_h);
    cudaGetSymbolAddress((void**)&ff2,  g_ff2);
    cudaGetSymbolAddress((void**)&bqkv, g_bqkv);

    __half *x16,*qkv16,*ctx16,*h16,*f116,*wqkv16,*wo16,*w116,*w216;
    cudaGetSymbolAddress((void**)&x16,   g_x16);
    cudaGetSymbolAddress((void**)&qkv16, g_qkv16);
    cudaGetSymbolAddress((void**)&ctx16, g_ctx16);
    cudaGetSymbolAddress((void**)&h16,   g_h16);
    cudaGetSymbolAddress((void**)&f116,  g_f116);
    cudaGetSymbolAddress((void**)&wqkv16,g_wqkv16);
    cudaGetSymbolAddress((void**)&wo16,  g_wo16);
    cudaGetSymbolAddress((void**)&w116,  g_w116);
    cudaGetSymbolAddress((void**)&w216,  g_w216);

    static int attr_set = 0;
    if (!attr_set) {
        cudaFuncSetAttribute(gemm_f16<0>, cudaFuncAttributeMaxDynamicSharedMemorySize, (int)sizeof(GSmem));
        cudaFuncSetAttribute(gemm_f16<1>, cudaFuncAttributeMaxDynamicSharedMemorySize, (int)sizeof(GSmem));
        cudaFuncSetAttribute(gemm_f16<2>, cudaFuncAttributeMaxDynamicSharedMemorySize, (int)sizeof(GSmem));
        cudaFuncSetAttribute(attn_mma, cudaFuncAttributeMaxDynamicSharedMemorySize, (int)sizeof(AttnSmem));
        attr_set = 1;
    }
    const int SG = (int)sizeof(GSmem);
    const int SA = (int)sizeof(AttnSmem);

    // ---- conversions + bias concat (one launch, 8 elems/thread) ----
    convert_all<<<8198, 256>>>(x, Wq, Wk, Wv, Wo, W1, W2, bq, bk, bv,
                               x16, wqkv16, wo16, w116, w216, bqkv);

    // ---- merged QKV projection ----
    dim3 gQKV(D3 / 128, MTOK / 128);
    gemm_f16<2><<<gQKV, 256, SG>>>(x16, wqkv16, bqkv, nullptr, qkv16, MTOK, D3, D);

    // ---- flash attention ----
    dim3 gAttn(SEQ / 128, NH, BATCH);
    attn_mma<<<gAttn, 256, SA>>>(qkv16, qkv16 + D, qkv16 + 2*D, ctx16, D3);

    // ---- O projection ----
    dim3 gO(D / 128, MTOK / 128);
    gemm_f16<0><<<gO, 256, SG>>>(ctx16, wo16, bo, attnres, nullptr, MTOK, D, D);

    // ---- LN1 ----
    add_ln<1><<<MTOK, 256>>>(attnres, x, ln1g, ln1b, h, h16);

    // ---- FFN ----
    dim3 gFF1(FF / 128, MTOK / 128);
    gemm_f16<1><<<gFF1, 256, SG>>>(h16, w116, b1, nullptr, f116, MTOK, FF, D);

    dim3 gFF2(D / 128, MTOK / 128);
    gemm_f16<0><<<gFF2, 256, SG>>>(f116, w216, b2, ff2, nullptr, MTOK, D, FF);

    // ---- LN2 ----
    add_ln<0><<<MTOK, 256>>>(ff2, h, ln2g, ln2b, out, nullptr);
}